// round 1
// baseline (speedup 1.0000x reference)
#include <cuda_runtime.h>
#include <cuda_bf16.h>

#define VOCAB 32000
#define EMBED 32
#define HID   16
#define SEQ   128
#define BATCH 32
#define G4    64      // 4*HID

// ---------------- scratch (device globals; no allocation) ----------------
__device__ float g_XG[SEQ * G4 * BATCH];   // [t][j][b]  input-side gate preacts + biases
__device__ float g_H [SEQ * HID * BATCH];  // [t][k][b]  hidden states
__device__ float g_rowsum[SEQ * BATCH];    // sum(exp(logits)) per (t,b)

// ---------------- f32x2 helpers ----------------
__device__ __forceinline__ unsigned long long pk2(float lo, float hi) {
    unsigned long long r;
    asm("mov.b64 %0, {%1, %2};" : "=l"(r) : "f"(lo), "f"(hi));
    return r;
}
__device__ __forceinline__ unsigned long long fma2(unsigned long long a,
                                                   unsigned long long b,
                                                   unsigned long long c) {
    unsigned long long d;
    asm("fma.rn.f32x2 %0, %1, %2, %3;" : "=l"(d) : "l"(a), "l"(b), "l"(c));
    return d;
}
__device__ __forceinline__ float hsum2(unsigned long long v) {
    float lo, hi;
    asm("mov.b64 {%0, %1}, %2;" : "=f"(lo), "=f"(hi) : "l"(v));
    return lo + hi;
}
__device__ __forceinline__ float dot16x2(const unsigned long long* w,
                                         const unsigned long long* x) {
    unsigned long long acc = 0ull;  // {+0.f, +0.f}
#pragma unroll
    for (int p = 0; p < 8; p++) acc = fma2(w[p], x[p], acc);
    return hsum2(acc);
}

__device__ __forceinline__ float fsigm(float x) {
    return __fdividef(1.f, 1.f + __expf(-x));
}
__device__ __forceinline__ float ftanh(float x) {
    float e = __expf(-2.f * x);
    return (1.f - e) * __fdividef(1.f, 1.f + e);
}

// ---------------- K1: gates from embedding (parallel over t) ----------------
__global__ __launch_bounds__(256) void k1_xgates(
    const int* __restrict__ idx, const float* __restrict__ emb,
    const float* __restrict__ Wih, const float* __restrict__ bih,
    const float* __restrict__ bhh) {
    __shared__ float xs[BATCH][EMBED + 1];  // +1 pad: avoid bank conflicts
    __shared__ float ws[G4][EMBED];
    __shared__ float bias[G4];
    const int t = blockIdx.x, tid = threadIdx.x;

    if (tid < BATCH) g_rowsum[t * BATCH + tid] = 0.f;   // zero lse scratch

    for (int i = tid; i < BATCH * EMBED; i += 256) {
        int b = i >> 5, e = i & 31;
        xs[b][e] = emb[idx[t * BATCH + b] * EMBED + e];
    }
    for (int i = tid; i < G4 * EMBED; i += 256) ws[i >> 5][i & 31] = Wih[i];
    if (tid < G4) bias[tid] = bih[tid] + bhh[tid];
    __syncthreads();

    for (int i = tid; i < G4 * BATCH; i += 256) {
        int j = i >> 5, b = i & 31;
        float acc = bias[j];
#pragma unroll
        for (int e = 0; e < EMBED; e++) acc = fmaf(xs[b][e], ws[j][e], acc);
        g_XG[(t * G4 + j) * BATCH + b] = acc;
    }
}

// ---------------- K2: sequential LSTM recurrence (1 block, 512 thr) -------
__global__ __launch_bounds__(512) void k2_recur(
    const float* __restrict__ Whh, const float* __restrict__ h0,
    const float* __restrict__ c0) {
    __shared__ float hs[HID * BATCH];  // [k][b]
    const int tid = threadIdx.x;
    const int h = tid >> 5;   // 0..15 (warp id)
    const int b = tid & 31;   // lane

    // W_hh rows for this unit's 4 gates, packed along k (broadcast loads)
    unsigned long long wi[8], wf[8], wg[8], wo[8];
#pragma unroll
    for (int p = 0; p < 8; p++) {
        wi[p] = pk2(Whh[(0 * HID + h) * HID + 2 * p], Whh[(0 * HID + h) * HID + 2 * p + 1]);
        wf[p] = pk2(Whh[(1 * HID + h) * HID + 2 * p], Whh[(1 * HID + h) * HID + 2 * p + 1]);
        wg[p] = pk2(Whh[(2 * HID + h) * HID + 2 * p], Whh[(2 * HID + h) * HID + 2 * p + 1]);
        wo[p] = pk2(Whh[(3 * HID + h) * HID + 2 * p], Whh[(3 * HID + h) * HID + 2 * p + 1]);
    }
    float c = c0[b * HID + h];
    hs[h * BATCH + b] = h0[b * HID + h];
    __syncthreads();

    for (int t = 0; t < SEQ; t++) {
        unsigned long long h2[8];
#pragma unroll
        for (int p = 0; p < 8; p++)
            h2[p] = pk2(hs[(2 * p) * BATCH + b], hs[(2 * p + 1) * BATCH + b]);

        const float* xg = &g_XG[t * G4 * BATCH];
        float gi = dot16x2(wi, h2) + xg[(0 * HID + h) * BATCH + b];
        float gf = dot16x2(wf, h2) + xg[(1 * HID + h) * BATCH + b];
        float gg = dot16x2(wg, h2) + xg[(2 * HID + h) * BATCH + b];
        float go = dot16x2(wo, h2) + xg[(3 * HID + h) * BATCH + b];

        float ii = fsigm(gi), ff = fsigm(gf), g_ = ftanh(gg), oo = fsigm(go);
        c = ff * c + ii * g_;
        float hn = oo * ftanh(c);

        __syncthreads();                 // all reads of hs done
        hs[h * BATCH + b] = hn;
        g_H[t * (HID * BATCH) + h * BATCH + b] = hn;  // [t][k][b], coalesced
        __syncthreads();
    }
}

// ---------------- K3: sum(exp(logits)) per row (recompute GEMM) -----------
__global__ __launch_bounds__(256) void k3_sumexp(
    const float* __restrict__ Wout, const float* __restrict__ bout) {
    const int t = blockIdx.y, tid = threadIdx.x;
    __shared__ unsigned long long h2s[BATCH][8];
    __shared__ float bsum[BATCH];
    if (tid < BATCH) bsum[tid] = 0.f;
    {
        int b = tid >> 3, p = tid & 7;  // 256 threads cover 32*8
        h2s[b][p] = pk2(g_H[t * (HID * BATCH) + (2 * p) * BATCH + b],
                        g_H[t * (HID * BATCH) + (2 * p + 1) * BATCH + b]);
    }
    __syncthreads();

    const int v0 = blockIdx.x * 512 + tid;
    const int v1 = v0 + 256;
    const bool ok0 = v0 < VOCAB, ok1 = v1 < VOCAB;

    unsigned long long w0[8], w1[8];
    float bb0 = 0.f, bb1 = 0.f;
    if (ok0) {
        const float4* wv = (const float4*)(Wout + v0 * HID);
#pragma unroll
        for (int q = 0; q < 4; q++) {
            float4 f = wv[q];
            w0[2 * q] = pk2(f.x, f.y); w0[2 * q + 1] = pk2(f.z, f.w);
        }
        bb0 = bout[v0];
    } else {
#pragma unroll
        for (int p = 0; p < 8; p++) w0[p] = 0ull;
    }
    if (ok1) {
        const float4* wv = (const float4*)(Wout + v1 * HID);
#pragma unroll
        for (int q = 0; q < 4; q++) {
            float4 f = wv[q];
            w1[2 * q] = pk2(f.x, f.y); w1[2 * q + 1] = pk2(f.z, f.w);
        }
        bb1 = bout[v1];
    } else {
#pragma unroll
        for (int p = 0; p < 8; p++) w1[p] = 0ull;
    }

    const int lane = tid & 31;
#pragma unroll 4
    for (int b = 0; b < BATCH; b++) {
        unsigned long long h2[8];
#pragma unroll
        for (int p = 0; p < 8; p++) h2[p] = h2s[b][p];  // uniform
        float l0 = dot16x2(w0, h2) + bb0;
        float l1 = dot16x2(w1, h2) + bb1;
        float e = (ok0 ? __expf(l0) : 0.f) + (ok1 ? __expf(l1) : 0.f);
#pragma unroll
        for (int m = 16; m > 0; m >>= 1) e += __shfl_xor_sync(0xffffffffu, e, m);
        if (lane == 0) atomicAdd(&bsum[b], e);
    }
    __syncthreads();
    if (tid < BATCH) atomicAdd(&g_rowsum[t * BATCH + tid], bsum[tid]);
}

// ---------------- K4: write logprobs = logit - lse (recompute GEMM) -------
__global__ __launch_bounds__(256) void k4_write(
    const float* __restrict__ Wout, const float* __restrict__ bout,
    float* __restrict__ out) {
    const int t = blockIdx.y, tid = threadIdx.x;
    __shared__ unsigned long long h2s[BATCH][8];
    __shared__ float lse[BATCH];
    if (tid < BATCH) lse[tid] = __logf(g_rowsum[t * BATCH + tid]);
    {
        int b = tid >> 3, p = tid & 7;
        h2s[b][p] = pk2(g_H[t * (HID * BATCH) + (2 * p) * BATCH + b],
                        g_H[t * (HID * BATCH) + (2 * p + 1) * BATCH + b]);
    }
    __syncthreads();

    const int v0 = blockIdx.x * 512 + tid;
    const int v1 = v0 + 256;
    const bool ok0 = v0 < VOCAB, ok1 = v1 < VOCAB;

    unsigned long long w0[8], w1[8];
    float bb0 = 0.f, bb1 = 0.f;
    if (ok0) {
        const float4* wv = (const float4*)(Wout + v0 * HID);
#pragma unroll
        for (int q = 0; q < 4; q++) {
            float4 f = wv[q];
            w0[2 * q] = pk2(f.x, f.y); w0[2 * q + 1] = pk2(f.z, f.w);
        }
        bb0 = bout[v0];
    } else {
#pragma unroll
        for (int p = 0; p < 8; p++) w0[p] = 0ull;
    }
    if (ok1) {
        const float4* wv = (const float4*)(Wout + v1 * HID);
#pragma unroll
        for (int q = 0; q < 4; q++) {
            float4 f = wv[q];
            w1[2 * q] = pk2(f.x, f.y); w1[2 * q + 1] = pk2(f.z, f.w);
        }
        bb1 = bout[v1];
    } else {
#pragma unroll
        for (int p = 0; p < 8; p++) w1[p] = 0ull;
    }

    float* orow = out + (size_t)t * BATCH * VOCAB;
#pragma unroll 4
    for (int b = 0; b < BATCH; b++) {
        unsigned long long h2[8];
#pragma unroll
        for (int p = 0; p < 8; p++) h2[p] = h2s[b][p];  // uniform
        float L = lse[b];
        float l0 = dot16x2(w0, h2) + bb0;
        float l1 = dot16x2(w1, h2) + bb1;
        if (ok0) orow[(size_t)b * VOCAB + v0] = l0 - L;  // lanes -> consecutive v
        if (ok1) orow[(size_t)b * VOCAB + v1] = l1 - L;
    }
}

// ---------------- launch ----------------
extern "C" void kernel_launch(void* const* d_in, const int* in_sizes, int n_in,
                              void* d_out, int out_size) {
    const int*   idx  = (const int*)  d_in[0];  // [128,32]
    const float* emb  = (const float*)d_in[1];  // [32000,32]
    const float* Wih  = (const float*)d_in[2];  // [64,32]
    const float* Whh  = (const float*)d_in[3];  // [64,16]
    const float* bih  = (const float*)d_in[4];  // [64]
    const float* bhh  = (const float*)d_in[5];  // [64]
    const float* Wout = (const float*)d_in[6];  // [32000,16]
    const float* bout = (const float*)d_in[7];  // [32000]
    const float* h0   = (const float*)d_in[8];  // [32,16]
    const float* c0   = (const float*)d_in[9];  // [32,16]
    float* out = (float*)d_out;

    k1_xgates<<<SEQ, 256>>>(idx, emb, Wih, bih, bhh);
    k2_recur<<<1, 512>>>(Whh, h0, c0);
    dim3 grid((VOCAB + 511) / 512, SEQ);
    k3_sumexp<<<grid, 256>>>(Wout, bout);
    k4_write<<<grid, 256>>>(Wout, bout, out);
}